// round 16
// baseline (speedup 1.0000x reference)
#include <cuda_runtime.h>
#include <cuda_fp16.h>
#include <mma.h>
#include <cstdint>
#include <math.h>

using namespace nvcuda;

#define LEN    19947
#define NHEAD  8
#define DH     32
#define NLVL   4
#define NPTS   4

#define PAD_ROWS 21393

// ---------------------------------------------------------------------------
// Scratch (device globals)
// ---------------------------------------------------------------------------
__device__ __half g_value_pad[PAD_ROWS * 256];
__device__ float  g_off [LEN * 256];
__device__ float  g_attn[LEN * 128];
__device__ __half g_mid_h[LEN * 256];
__device__ __half g_q_h[LEN * 256];
__device__ __half g_f_h[LEN * 256];
__device__ __half g_w_h[896 * 256];
__device__ float  g_brep[2 * 16 * 256];   // [0]=b_out rep, [1]=b_off rep (16 rows)

__device__ __forceinline__ uint32_t smem_u32(const void* p) {
    uint32_t a;
    asm("{ .reg .u64 t; cvta.to.shared.u64 t, %1; cvt.u32.u64 %0, t; }" : "=r"(a) : "l"(p));
    return a;
}

__device__ __forceinline__ int pad_row(int gr) {
    int r, W, Wp, st;
    if (gr < 15000)      { r = gr;          W = 150; Wp = 153; st = 0; }
    else if (gr < 18750) { r = gr - 15000;  W = 75;  Wp = 78;  st = 15759; }
    else if (gr < 19700) { r = gr - 18750;  W = 38;  Wp = 41;  st = 19893; }
    else                 { r = gr - 19700;  W = 19;  Wp = 22;  st = 21041; }
    int y = r / W, x = r - y * W;
    return st + (y + 1) * Wp + (x + 1);
}

// padded row index -> is it a border row (never written by value epilogue)?
__device__ __forceinline__ bool pad_is_border(int pr) {
    int r, W, H, Wp;
    if (pr < 15759)      { r = pr;          W = 150; H = 100; Wp = 153; }
    else if (pr < 19893) { r = pr - 15759;  W = 75;  H = 50;  Wp = 78;  }
    else if (pr < 21041) { r = pr - 19893;  W = 38;  H = 25;  Wp = 41;  }
    else                 { r = pr - 21041;  W = 19;  H = 13;  Wp = 22;  }
    int y = r / Wp, x = r - y * Wp;
    return (y == 0) | (y > H) | (x == 0) | (x > W);
}

// ---------------------------------------------------------------------------
// Single fused prep kernel (border-only zeroing)
// ---------------------------------------------------------------------------
#define PREP_A (PAD_ROWS * 32)
#define PREP_B (896 * 256)
#define PREP_C (2 * LEN * 64)
#define PREP_D (2 * 16 * 256)
#define PREP_TOTAL (PREP_A + PREP_B + PREP_C + PREP_D)

__global__ void prep_all_kernel(const float* __restrict__ W_val,
                                const float* __restrict__ W_off,
                                const float* __restrict__ W_attn,
                                const float* __restrict__ W_out,
                                const float* __restrict__ query,
                                const float* __restrict__ inflat,
                                const float* __restrict__ b_out,
                                const float* __restrict__ b_off,
                                __half* __restrict__ vp,
                                __half* __restrict__ wh,
                                __half* __restrict__ qh,
                                __half* __restrict__ fh,
                                float* __restrict__ brep)
{
    int id = blockIdx.x * blockDim.x + threadIdx.x;
    if (id < PREP_A) {
        int pr = id >> 5;                 // padded row (32 x 16B units per row)
        if (pad_is_border(pr))
            *reinterpret_cast<uint4*>(vp + (size_t)id * 8) = make_uint4(0, 0, 0, 0);
    } else if (id < PREP_A + PREP_B) {
        int e = id - PREP_A;
        int n = e >> 8;
        int k = e & 255;
        float x;
        if (n < 256)      x = W_val [k * 256 + n];
        else if (n < 512) x = W_off [k * 256 + (n - 256)];
        else if (n < 640) x = W_attn[k * 128 + (n - 512)];
        else              x = W_out [k * 256 + (n - 640)];
        wh[e] = __float2half_rn(x);
    } else if (id < PREP_A + PREP_B + PREP_C) {
        int e = id - PREP_A - PREP_B;
        const int total4 = LEN * 64;
        const float* src;
        __half* dst;
        int i4 = e;
        if (e < total4) { src = query;  dst = qh; }
        else            { src = inflat; dst = fh; i4 -= total4; }
        float4 v = *reinterpret_cast<const float4*>(src + (size_t)i4 * 4);
        __half h[4] = {__float2half_rn(v.x), __float2half_rn(v.y),
                       __float2half_rn(v.z), __float2half_rn(v.w)};
        *reinterpret_cast<uint2*>(dst + (size_t)i4 * 4) = *reinterpret_cast<uint2*>(h);
    } else if (id < PREP_TOTAL) {
        int e = id - PREP_A - PREP_B - PREP_C;
        int half_sel = e >> 12;          // 0: b_out, 1: b_off
        int col = e & 255;
        brep[e] = half_sel ? b_off[col] : b_out[col];
    }
}

// ---------------------------------------------------------------------------
// cp.async macros
// ---------------------------------------------------------------------------
#define CP16(dst, src, sz) \
    asm volatile("cp.async.cg.shared.global [%0], [%1], 16, %2;" \
                 :: "r"(dst), "l"(src), "r"(sz))
#define CP_COMMIT() asm volatile("cp.async.commit_group;")
#define CP_WAIT1()  asm volatile("cp.async.wait_group 1;")
#define CP_WAIT0()  asm volatile("cp.async.wait_group 0;")

// Block tile 64x128, BK=64, 2-stage, 128 threads / 4 warps, warp tile 32x64
#define ASTR 72
#define A64_BUF (64 * ASTR * 2)        // 9216
#define B64_BUF (128 * ASTR * 2)       // 18432
#define STAGE64 (A64_BUF + B64_BUF)    // 27648
#define CSTRIDE 132
#define H_SMEM (2 * STAGE64)           // 55296

// ---------------------------------------------------------------------------
// GEMM mainloop: block tile 64x128, warp tile 32x64, BK=64, 2-stage.
// ---------------------------------------------------------------------------
__device__ __forceinline__ void gemm_mainloop(
    const __half* __restrict__ A, const __half* __restrict__ B,
    char* smem, int block_m, int block_n, int Mrows,
    wmma::fragment<wmma::accumulator, 16, 16, 16, float> (&acc)[2][4])
{
    const int tid  = threadIdx.x;
    const int warp = tid >> 5;
    const int wm   = warp & 1;
    const int wn   = warp >> 1;
    const uint32_t sb = smem_u32(smem);

#pragma unroll
    for (int i = 0; i < 2; i++)
#pragma unroll
        for (int j = 0; j < 4; j++) wmma::fill_fragment(acc[i][j], 0.f);

    auto issue = [&](int chunk) {
        const int s = chunk & 1;
        const int k0 = chunk * 64;
        const uint32_t sbase = sb + s * STAGE64;
#pragma unroll
        for (int h = 0; h < 4; h++) {
            const int c   = tid + h * 128;
            const int row = c >> 3;
            const int prt = (c & 7) * 8;
            const uint32_t so = (uint32_t)(row * ASTR + prt) * 2;
            const int ga  = block_m + row;
            const int asz = (ga < Mrows) ? 16 : 0;
            CP16(sbase + so, A + (size_t)ga * 256 + k0 + prt, asz);
        }
#pragma unroll
        for (int h = 0; h < 8; h++) {
            const int c   = tid + h * 128;
            const int row = c >> 3;
            const int prt = (c & 7) * 8;
            const uint32_t so = (uint32_t)(row * ASTR + prt) * 2;
            CP16(sbase + A64_BUF + so, B + (size_t)(block_n + row) * 256 + k0 + prt, 16);
        }
    };

    issue(0);
    CP_COMMIT();

    for (int chunk = 0; chunk < 4; chunk++) {
        if (chunk < 3) { issue(chunk + 1); CP_COMMIT(); CP_WAIT1(); }
        else           { CP_WAIT0(); }
        __syncthreads();

        const int s = chunk & 1;
        const __half* ab = reinterpret_cast<const __half*>(smem + s * STAGE64);
        const __half* bb = ab + 64 * ASTR;

#pragma unroll
        for (int ks = 0; ks < 64; ks += 16) {
            wmma::fragment<wmma::matrix_a, 16, 16, 16, __half, wmma::row_major> fa[2];
            wmma::fragment<wmma::matrix_b, 16, 16, 16, __half, wmma::col_major> fb[4];
#pragma unroll
            for (int i = 0; i < 2; i++)
                wmma::load_matrix_sync(fa[i], ab + (wm * 32 + i * 16) * ASTR + ks, ASTR);
#pragma unroll
            for (int j = 0; j < 4; j++)
                wmma::load_matrix_sync(fb[j], bb + (wn * 64 + j * 16) * ASTR + ks, ASTR);
#pragma unroll
            for (int i = 0; i < 2; i++)
#pragma unroll
                for (int j = 0; j < 4; j++) wmma::mma_sync(acc[i][j], fa[i], fb[j], acc[i][j]);
        }
        __syncthreads();
    }
}

__device__ __forceinline__ void stage_acc(
    wmma::fragment<wmma::accumulator, 16, 16, 16, float> (&acc)[2][4], char* smem)
{
    const int warp = threadIdx.x >> 5;
    const int wm   = warp & 1;
    const int wn   = warp >> 1;
    float* stage = reinterpret_cast<float*>(smem);
#pragma unroll
    for (int i = 0; i < 2; i++)
#pragma unroll
        for (int j = 0; j < 4; j++)
            wmma::store_matrix_sync(stage + (wm * 32 + i * 16) * CSTRIDE + wn * 64 + j * 16,
                                    acc[i][j], CSTRIDE, wmma::mem_row_major);
    __syncthreads();
}

__device__ __forceinline__ void direct_epilogue(
    wmma::fragment<wmma::accumulator, 16, 16, 16, float> (&acc)[2][4],
    const float* __restrict__ brep, float* __restrict__ C,
    int block_m, int block_n)
{
    const int warp = threadIdx.x >> 5;
    const int wm   = warp & 1;
    const int wn   = warp >> 1;
#pragma unroll
    for (int j = 0; j < 4; j++) {
        wmma::fragment<wmma::accumulator, 16, 16, 16, float> bf;
        wmma::load_matrix_sync(bf, brep + block_n + wn * 64 + j * 16, 256, wmma::mem_row_major);
#pragma unroll
        for (int i = 0; i < 2; i++) {
            wmma::fragment<wmma::accumulator, 16, 16, 16, float> t;
#pragma unroll
            for (int e = 0; e < t.num_elements; e++) t.x[e] = acc[i][j].x[e] + bf.x[e];
            wmma::store_matrix_sync(C + (size_t)(block_m + wm * 32 + i * 16) * 256
                                      + block_n + wn * 64 + j * 16,
                                    t, 256, wmma::mem_row_major);
        }
    }
}

// ---------------------------------------------------------------------------
// Fused projection kernel (persistent): 1560 tiles, grid 390 -> exactly 4 each.
// ---------------------------------------------------------------------------
__global__ __launch_bounds__(128, 3)
void proj_fused_kernel(const __half* __restrict__ Af,
                       const __half* __restrict__ Aq,
                       const __half* __restrict__ Bv,
                       const __half* __restrict__ Boa,
                       const float* __restrict__ b_val,
                       const float* __restrict__ b_attn,
                       const float* __restrict__ brep_off,
                       const unsigned char* __restrict__ mask,
                       __half* __restrict__ Cval,
                       float* __restrict__ Coff,
                       float* __restrict__ Cattn,
                       int Mrows, int ntiles)
{
    extern __shared__ char smem[];
    const int tid = threadIdx.x;

    for (int t = blockIdx.x; t < ntiles; t += gridDim.x) {
        const int bx = t % 5;
        const int mt = t / 5;
        const bool is_val = (bx < 2);
        const int block_m = mt * 64;
        const int block_n = (is_val ? bx : bx - 2) * 128;

        wmma::fragment<wmma::accumulator, 16, 16, 16, float> acc[2][4];
        gemm_mainloop(is_val ? Af : Aq, is_val ? Bv : Boa, smem, block_m, block_n, Mrows, acc);

        if (bx == 2 || bx == 3) {
            if (block_m + 64 <= Mrows) {
                direct_epilogue(acc, brep_off, Coff, block_m, block_n);
                __syncthreads();
                continue;
            }
        }

        stage_acc(acc, smem);
        const float* stage = reinterpret_cast<const float*>(smem);
        const int r    = tid >> 1;
        const int colb = (tid & 1) * 64;
        const int gr   = block_m + r;
        if (gr < Mrows) {
            if (is_val) {
                const int prow = pad_row(gr);
                const float scale = (mask != nullptr && mask[gr]) ? 0.f : 1.f;
#pragma unroll
                for (int g = 0; g < 64; g += 16) {
                    const int gcol = block_n + colb + g;
                    __half hbuf[16];
#pragma unroll
                    for (int c = 0; c < 16; c++)
                        hbuf[c] = __float2half_rn((stage[r * CSTRIDE + colb + g + c] + __ldg(b_val + gcol + c)) * scale);
#pragma unroll
                    for (int c = 0; c < 16; c += 8)
                        *reinterpret_cast<uint4*>(Cval + (size_t)prow * 256 + gcol + c) =
                            *reinterpret_cast<uint4*>(hbuf + c);
                }
            } else if (bx == 4) {
#pragma unroll
                for (int g = 0; g < 64; g += 16) {
                    const int gc = colb + g;
                    float v[16];
#pragma unroll
                    for (int c = 0; c < 16; c++)
                        v[c] = stage[r * CSTRIDE + colb + g + c] + __ldg(b_attn + gc + c);
                    float mx = -1e30f;
#pragma unroll
                    for (int c = 0; c < 16; c++) mx = fmaxf(mx, v[c]);
                    float sum = 0.f;
#pragma unroll
                    for (int c = 0; c < 16; c++) { v[c] = __expf(v[c] - mx); sum += v[c]; }
                    float inv = 1.f / sum;
#pragma unroll
                    for (int c = 0; c < 16; c += 4) {
                        float4 o = make_float4(v[c]*inv, v[c+1]*inv, v[c+2]*inv, v[c+3]*inv);
                        *reinterpret_cast<float4*>(Cattn + (size_t)gr * 128 + gc + c) = o;
                    }
                }
            } else {
#pragma unroll
                for (int g = 0; g < 64; g += 16) {
                    const int gcol = block_n + colb + g;
                    float v[16];
#pragma unroll
                    for (int c = 0; c < 16; c++)
                        v[c] = stage[r * CSTRIDE + colb + g + c] + __ldg(brep_off + gcol + c);
#pragma unroll
                    for (int c = 0; c < 16; c += 4) {
                        float4 o = make_float4(v[c], v[c+1], v[c+2], v[c+3]);
                        *reinterpret_cast<float4*>(Coff + (size_t)gr * 256 + gcol + c) = o;
                    }
                }
            }
        }
        __syncthreads();
    }
}

// ---------------------------------------------------------------------------
// Output projection kernel (persistent): 624 tiles, grid 312 -> exactly 2 each.
// ---------------------------------------------------------------------------
__global__ __launch_bounds__(128, 3)
void proj_out_kernel(const __half* __restrict__ A,
                     const __half* __restrict__ B,
                     const float* __restrict__ brep_out,
                     float* __restrict__ C,
                     int Mrows, int ntiles)
{
    extern __shared__ char smem[];
    const int tid = threadIdx.x;

    for (int t = blockIdx.x; t < ntiles; t += gridDim.x) {
        const int block_n = (t & 1) * 128;
        const int block_m = (t >> 1) * 64;

        wmma::fragment<wmma::accumulator, 16, 16, 16, float> acc[2][4];
        gemm_mainloop(A, B, smem, block_m, block_n, Mrows, acc);

        if (block_m + 64 <= Mrows) {
            direct_epilogue(acc, brep_out, C, block_m, block_n);
        } else {
            stage_acc(acc, smem);
            const float* stage = reinterpret_cast<const float*>(smem);
            const int r    = tid >> 1;
            const int colb = (tid & 1) * 64;
            const int gr   = block_m + r;
            if (gr < Mrows) {
#pragma unroll
                for (int g = 0; g < 64; g += 16) {
                    const int gcol = block_n + colb + g;
                    float v[16];
#pragma unroll
                    for (int c = 0; c < 16; c++)
                        v[c] = stage[r * CSTRIDE + colb + g + c] + __ldg(brep_out + gcol + c);
#pragma unroll
                    for (int c = 0; c < 16; c += 4) {
                        float4 o = make_float4(v[c], v[c+1], v[c+2], v[c+3]);
                        *reinterpret_cast<float4*>(C + (size_t)gr * 256 + gcol + c) = o;
                    }
                }
            }
        }
        __syncthreads();
    }
}

// ---------------------------------------------------------------------------
// Sampler v7 (proven best)
// ---------------------------------------------------------------------------
__global__ __launch_bounds__(256)
void sample_kernel(const __half* __restrict__ value,
                   const float* __restrict__ off,
                   const float* __restrict__ aw,
                   const float* __restrict__ refp,
                   __half* __restrict__ mid)
{
    const int q    = blockIdx.x;
    const int m    = threadIdx.x >> 5;
    const int lane = threadIdx.x & 31;
    const int p2   = lane >> 3;
    const int c4   = lane & 7;

    const float offv = __ldg(off  + (size_t)q * 256 + m * 32 + lane);
    const float awv  = __ldg(aw   + (size_t)q * 128 + m * 16 + (lane & 15));
    const float rfv  = __ldg(refp + (size_t)q * 8 + (lane & 7));

    const int pt0 = lane & 15;
    const int l0  = pt0 >> 2;
    const float rx = __shfl_sync(0xffffffffu, rfv, l0 * 2 + 0);
    const float ry = __shfl_sync(0xffffffffu, rfv, l0 * 2 + 1);
    const float ox = __shfl_sync(0xffffffffu, offv, pt0 * 2 + 0);
    const float oy = __shfl_sync(0xffffffffu, offv, pt0 * 2 + 1);

    const float Wf = (l0 == 0) ? 150.f : (l0 == 1) ? 75.f : (l0 == 2) ? 38.f : 19.f;
    const float Hf = (l0 == 0) ? 100.f : (l0 == 1) ? 50.f : (l0 == 2) ? 25.f : 13.f;
    const int   Wp0 = (l0 == 0) ? 153 : (l0 == 1) ? 78 : (l0 == 2) ? 41 : 22;
    const int   SB0 = (l0 == 0) ? 154 : (l0 == 1) ? 15838 : (l0 == 2) ? 19935 : 21064;

    float x = fmaf(rx, Wf, ox) - 0.5f;
    float y = fmaf(ry, Hf, oy) - 0.5f;
    x = fminf(fmaxf(x, -1.f), Wf);
    y = fminf(fmaxf(y, -1.f), Hf);

    const float x0f = floorf(x), y0f = floorf(y);
    const float wx1 = x - x0f, wx0 = 1.f - wx1;
    const float wy1 = y - y0f, wy0 = 1.f - wy1;
    const int i00r = SB0 + (int)y0f * Wp0 + (int)x0f;

    __half2 pk01h = __floats2half2_rn(wx0 * wy0 * awv, wx1 * wy0 * awv);
    __half2 pk23h = __floats2half2_rn(wx0 * wy1 * awv, wx1 * wy1 * awv);
    const uint32_t pk01 = *reinterpret_cast<uint32_t*>(&pk01h);
    const uint32_t pk23 = *reinterpret_cast<uint32_t*>(&pk23h);

    const __half* vbase = value + m * DH + c4 * 4;
    float acc0 = 0.f, acc1 = 0.f, acc2 = 0.f, acc3 = 0.f;

    const int WPT[NLVL] = {153, 78, 41, 22};

#pragma unroll
    for (int l = 0; l < NLVL; l++) {
        const int src = l * 4 + p2;
        const int i00 = __shfl_sync(0xffffffffu, i00r, src);
        const uint32_t a01 = __shfl_sync(0xffffffffu, pk01, src);
        const uint32_t a23 = __shfl_sync(0xffffffffu, pk23, src);

        const __half2 h01 = *reinterpret_cast<const __half2*>(&a01);
        const __half2 h23 = *reinterpret_cast<const __half2*>(&a23);
        const __half2 W00 = __low2half2(h01),  W01 = __high2half2(h01);
        const __half2 W10 = __low2half2(h23),  W11 = __high2half2(h23);

        const int Wp = WPT[l];
        const __half* p00 = vbase + (size_t)i00 * 256;

        const uint2 u00 = __ldg(reinterpret_cast<const uint2*>(p00));
        const uint2 u01 = __ldg(reinterpret_cast<const uint2*>(p00 + 256));
        const uint2 u10 = __ldg(reinterpret_cast<const uint2*>(p00 + Wp * 256));
        const uint2 u11 = __ldg(reinterpret_cast<const uint2*>(p00 + (Wp + 1) * 256));

        __half2 sa = __hmul2(W00, *reinterpret_cast<const __half2*>(&u00.x));
        sa = __hfma2(W01, *reinterpret_cast<const __half2*>(&u01.x), sa);
        sa = __hfma2(W10, *reinterpret_cast<const __half2*>(&u10.x), sa);
        sa = __hfma2(W11, *reinterpret_cast<const __half2*>(&u11.x), sa);

        __half2 sb = __hmul2(W00, *reinterpret_cast<const __half2*>(&u00.y));
        sb = __hfma2(W01, *reinterpret_cast<const __half2*>(&u01.y), sb);
        sb = __hfma2(W10, *reinterpret_cast<const __half2*>(&u10.y), sb);
        sb = __hfma2(W11, *reinterpret_cast<const __half2*>(&u11.y), sb);

        const float2 fa = __half22float2(sa);
        const float2 fb = __half22float2(sb);
        acc0 += fa.x;
        acc1 += fa.y;
        acc2 += fb.x;
        acc3 += fb.y;
    }

    acc0 += __shfl_xor_sync(0xffffffffu, acc0, 8);
    acc1 += __shfl_xor_sync(0xffffffffu, acc1, 8);
    acc2 += __shfl_xor_sync(0xffffffffu, acc2, 8);
    acc3 += __shfl_xor_sync(0xffffffffu, acc3, 8);
    acc0 += __shfl_xor_sync(0xffffffffu, acc0, 16);
    acc1 += __shfl_xor_sync(0xffffffffu, acc1, 16);
    acc2 += __shfl_xor_sync(0xffffffffu, acc2, 16);
    acc3 += __shfl_xor_sync(0xffffffffu, acc3, 16);

    if (lane < 8) {
        __half2 h0 = __floats2half2_rn(acc0, acc1);
        __half2 h1 = __floats2half2_rn(acc2, acc3);
        uint2 u;
        u.x = *reinterpret_cast<uint32_t*>(&h0);
        u.y = *reinterpret_cast<uint32_t*>(&h1);
        *reinterpret_cast<uint2*>(mid + (size_t)q * 256 + m * DH + c4 * 4) = u;
    }
}

// ---------------------------------------------------------------------------
// Launch
// ---------------------------------------------------------------------------
extern "C" void kernel_launch(void* const* d_in, const int* in_sizes, int n_in,
                              void* d_out, int out_size)
{
    const float* query  = (const float*)d_in[0];
    const float* refp   = (const float*)d_in[1];
    const float* inflat = (const float*)d_in[2];
    const unsigned char* pmask = (const unsigned char*)d_in[3];
    const float* W_off  = (const float*)d_in[4];
    const float* b_off  = (const float*)d_in[5];
    const float* W_attn = (const float*)d_in[6];
    const float* b_attn = (const float*)d_in[7];
    const float* W_val  = (const float*)d_in[8];
    const float* b_val  = (const float*)d_in[9];
    const float* W_out  = (const float*)d_in[10];
    const float* b_out  = (const float*)d_in[11];
    float* out = (float*)d_out;

    __half* pvalp; cudaGetSymbolAddress((void**)&pvalp, g_value_pad);
    float*  poff;  cudaGetSymbolAddress((void**)&poff,  g_off);
    float*  pattn; cudaGetSymbolAddress((void**)&pattn, g_attn);
    float*  brep;  cudaGetSymbolAddress((void**)&brep,  g_brep);
    __half *q_h, *f_h, *w_h, *mid_h;
    cudaGetSymbolAddress((void**)&q_h,   g_q_h);
    cudaGetSymbolAddress((void**)&f_h,   g_f_h);
    cudaGetSymbolAddress((void**)&w_h,   g_w_h);
    cudaGetSymbolAddress((void**)&mid_h, g_mid_h);

    cudaFuncSetAttribute(proj_fused_kernel,
                         cudaFuncAttributeMaxDynamicSharedMemorySize, H_SMEM);
    cudaFuncSetAttribute(proj_out_kernel,
                         cudaFuncAttributeMaxDynamicSharedMemorySize, H_SMEM);

    const int Mr = LEN;
    const int mtiles = (Mr + 63) / 64;            // 312

    prep_all_kernel<<<(PREP_TOTAL + 255) / 256, 256>>>(
        W_val, W_off, W_attn, W_out, query, inflat, b_out, b_off,
        pvalp, w_h, q_h, f_h, brep);

    const __half* wv  = w_h;
    const __half* woa = w_h + 256 * 256;
    const __half* wu  = w_h + 640 * 256;
    const float* brep_out = brep;
    const float* brep_off = brep + 16 * 256;

    // 1. fused projections: 1560 tiles over 390 CTAs -> exactly 4 each
    proj_fused_kernel<<<390, 128, H_SMEM>>>(
        f_h, q_h, wv, woa, b_val, b_attn, brep_off, pmask, pvalp, poff, pattn,
        Mr, 5 * mtiles);
    // 2. sampler (v7)
    sample_kernel<<<Mr, 256>>>(pvalp, poff, pattn, refp, mid_h);
    // 3. output projection: 624 tiles over 312 CTAs -> exactly 2 each
    proj_out_kernel<<<312, 128, H_SMEM>>>(mid_h, wu, brep_out, out, Mr, 2 * mtiles);
}

// round 17
// speedup vs baseline: 1.0822x; 1.0822x over previous
#include <cuda_runtime.h>
#include <cuda_fp16.h>
#include <mma.h>
#include <cstdint>
#include <math.h>

using namespace nvcuda;

#define LEN    19947
#define NHEAD  8
#define DH     32
#define NLVL   4
#define NPTS   4

#define PAD_ROWS 21393

// ---------------------------------------------------------------------------
// Scratch (device globals)
// ---------------------------------------------------------------------------
__device__ __half g_value_pad[PAD_ROWS * 256];
__device__ float  g_off [LEN * 256];
__device__ float  g_attn[LEN * 128];
__device__ __half g_mid_h[LEN * 256];
__device__ __half g_q_h[LEN * 256];
__device__ __half g_f_h[LEN * 256];
__device__ __half g_w_h[896 * 256];
__device__ float  g_brep[2 * 16 * 256];   // [0]=b_out rep, [1]=b_off rep (16 rows)

__device__ __forceinline__ uint32_t smem_u32(const void* p) {
    uint32_t a;
    asm("{ .reg .u64 t; cvta.to.shared.u64 t, %1; cvt.u32.u64 %0, t; }" : "=r"(a) : "l"(p));
    return a;
}

__device__ __forceinline__ int pad_row(int gr) {
    int r, W, Wp, st;
    if (gr < 15000)      { r = gr;          W = 150; Wp = 153; st = 0; }
    else if (gr < 18750) { r = gr - 15000;  W = 75;  Wp = 78;  st = 15759; }
    else if (gr < 19700) { r = gr - 18750;  W = 38;  Wp = 41;  st = 19893; }
    else                 { r = gr - 19700;  W = 19;  Wp = 22;  st = 21041; }
    int y = r / W, x = r - y * W;
    return st + (y + 1) * Wp + (x + 1);
}

// padded row index -> is it a border row (never written by value epilogue)?
__device__ __forceinline__ bool pad_is_border(int pr) {
    int r, W, H, Wp;
    if (pr < 15759)      { r = pr;          W = 150; H = 100; Wp = 153; }
    else if (pr < 19893) { r = pr - 15759;  W = 75;  H = 50;  Wp = 78;  }
    else if (pr < 21041) { r = pr - 19893;  W = 38;  H = 25;  Wp = 41;  }
    else                 { r = pr - 21041;  W = 19;  H = 13;  Wp = 22;  }
    int y = r / Wp, x = r - y * Wp;
    return (y == 0) | (y > H) | (x == 0) | (x > W);
}

// ---------------------------------------------------------------------------
// Single fused prep kernel (border-only zeroing)
// ---------------------------------------------------------------------------
#define PREP_A (PAD_ROWS * 32)
#define PREP_B (896 * 256)
#define PREP_C (2 * LEN * 64)
#define PREP_D (2 * 16 * 256)
#define PREP_TOTAL (PREP_A + PREP_B + PREP_C + PREP_D)

__global__ void prep_all_kernel(const float* __restrict__ W_val,
                                const float* __restrict__ W_off,
                                const float* __restrict__ W_attn,
                                const float* __restrict__ W_out,
                                const float* __restrict__ query,
                                const float* __restrict__ inflat,
                                const float* __restrict__ b_out,
                                const float* __restrict__ b_off,
                                __half* __restrict__ vp,
                                __half* __restrict__ wh,
                                __half* __restrict__ qh,
                                __half* __restrict__ fh,
                                float* __restrict__ brep)
{
    int id = blockIdx.x * blockDim.x + threadIdx.x;
    if (id < PREP_A) {
        int pr = id >> 5;                 // padded row (32 x 16B units per row)
        if (pad_is_border(pr))
            *reinterpret_cast<uint4*>(vp + (size_t)id * 8) = make_uint4(0, 0, 0, 0);
    } else if (id < PREP_A + PREP_B) {
        int e = id - PREP_A;
        int n = e >> 8;
        int k = e & 255;
        float x;
        if (n < 256)      x = W_val [k * 256 + n];
        else if (n < 512) x = W_off [k * 256 + (n - 256)];
        else if (n < 640) x = W_attn[k * 128 + (n - 512)];
        else              x = W_out [k * 256 + (n - 640)];
        wh[e] = __float2half_rn(x);
    } else if (id < PREP_A + PREP_B + PREP_C) {
        int e = id - PREP_A - PREP_B;
        const int total4 = LEN * 64;
        const float* src;
        __half* dst;
        int i4 = e;
        if (e < total4) { src = query;  dst = qh; }
        else            { src = inflat; dst = fh; i4 -= total4; }
        float4 v = *reinterpret_cast<const float4*>(src + (size_t)i4 * 4);
        __half h[4] = {__float2half_rn(v.x), __float2half_rn(v.y),
                       __float2half_rn(v.z), __float2half_rn(v.w)};
        *reinterpret_cast<uint2*>(dst + (size_t)i4 * 4) = *reinterpret_cast<uint2*>(h);
    } else if (id < PREP_TOTAL) {
        int e = id - PREP_A - PREP_B - PREP_C;
        int half_sel = e >> 12;          // 0: b_out, 1: b_off
        int col = e & 255;
        brep[e] = half_sel ? b_off[col] : b_out[col];
    }
}

// ---------------------------------------------------------------------------
// cp.async macros
// ---------------------------------------------------------------------------
#define CP16(dst, src, sz) \
    asm volatile("cp.async.cg.shared.global [%0], [%1], 16, %2;" \
                 :: "r"(dst), "l"(src), "r"(sz))
#define CP_COMMIT() asm volatile("cp.async.commit_group;")
#define CP_WAIT1()  asm volatile("cp.async.wait_group 1;")
#define CP_WAIT0()  asm volatile("cp.async.wait_group 0;")

// Block tile 64x128, BK=64, 2-stage, 128 threads / 4 warps, warp tile 32x64
#define ASTR 72
#define A64_BUF (64 * ASTR * 2)        // 9216
#define B64_BUF (128 * ASTR * 2)       // 18432
#define STAGE64 (A64_BUF + B64_BUF)    // 27648
#define CSTRIDE 132
#define H_SMEM (2 * STAGE64)           // 55296
#define PGRID 444                      // 3 CTAs x 148 SMs

// ---------------------------------------------------------------------------
// GEMM mainloop: block tile 64x128, warp tile 32x64, BK=64, 2-stage.
// ---------------------------------------------------------------------------
__device__ __forceinline__ void gemm_mainloop(
    const __half* __restrict__ A, const __half* __restrict__ B,
    char* smem, int block_m, int block_n, int Mrows,
    wmma::fragment<wmma::accumulator, 16, 16, 16, float> (&acc)[2][4])
{
    const int tid  = threadIdx.x;
    const int warp = tid >> 5;
    const int wm   = warp & 1;
    const int wn   = warp >> 1;
    const uint32_t sb = smem_u32(smem);

#pragma unroll
    for (int i = 0; i < 2; i++)
#pragma unroll
        for (int j = 0; j < 4; j++) wmma::fill_fragment(acc[i][j], 0.f);

    auto issue = [&](int chunk) {
        const int s = chunk & 1;
        const int k0 = chunk * 64;
        const uint32_t sbase = sb + s * STAGE64;
#pragma unroll
        for (int h = 0; h < 4; h++) {
            const int c   = tid + h * 128;
            const int row = c >> 3;
            const int prt = (c & 7) * 8;
            const uint32_t so = (uint32_t)(row * ASTR + prt) * 2;
            const int ga  = block_m + row;
            const int asz = (ga < Mrows) ? 16 : 0;
            CP16(sbase + so, A + (size_t)ga * 256 + k0 + prt, asz);
        }
#pragma unroll
        for (int h = 0; h < 8; h++) {
            const int c   = tid + h * 128;
            const int row = c >> 3;
            const int prt = (c & 7) * 8;
            const uint32_t so = (uint32_t)(row * ASTR + prt) * 2;
            CP16(sbase + A64_BUF + so, B + (size_t)(block_n + row) * 256 + k0 + prt, 16);
        }
    };

    issue(0);
    CP_COMMIT();

    for (int chunk = 0; chunk < 4; chunk++) {
        if (chunk < 3) { issue(chunk + 1); CP_COMMIT(); CP_WAIT1(); }
        else           { CP_WAIT0(); }
        __syncthreads();

        const int s = chunk & 1;
        const __half* ab = reinterpret_cast<const __half*>(smem + s * STAGE64);
        const __half* bb = ab + 64 * ASTR;

#pragma unroll
        for (int ks = 0; ks < 64; ks += 16) {
            wmma::fragment<wmma::matrix_a, 16, 16, 16, __half, wmma::row_major> fa[2];
            wmma::fragment<wmma::matrix_b, 16, 16, 16, __half, wmma::col_major> fb[4];
#pragma unroll
            for (int i = 0; i < 2; i++)
                wmma::load_matrix_sync(fa[i], ab + (wm * 32 + i * 16) * ASTR + ks, ASTR);
#pragma unroll
            for (int j = 0; j < 4; j++)
                wmma::load_matrix_sync(fb[j], bb + (wn * 64 + j * 16) * ASTR + ks, ASTR);
#pragma unroll
            for (int i = 0; i < 2; i++)
#pragma unroll
                for (int j = 0; j < 4; j++) wmma::mma_sync(acc[i][j], fa[i], fb[j], acc[i][j]);
        }
        __syncthreads();
    }
}

__device__ __forceinline__ void stage_acc(
    wmma::fragment<wmma::accumulator, 16, 16, 16, float> (&acc)[2][4], char* smem)
{
    const int warp = threadIdx.x >> 5;
    const int wm   = warp & 1;
    const int wn   = warp >> 1;
    float* stage = reinterpret_cast<float*>(smem);
#pragma unroll
    for (int i = 0; i < 2; i++)
#pragma unroll
        for (int j = 0; j < 4; j++)
            wmma::store_matrix_sync(stage + (wm * 32 + i * 16) * CSTRIDE + wn * 64 + j * 16,
                                    acc[i][j], CSTRIDE, wmma::mem_row_major);
    __syncthreads();
}

__device__ __forceinline__ void direct_epilogue(
    wmma::fragment<wmma::accumulator, 16, 16, 16, float> (&acc)[2][4],
    const float* __restrict__ brep, float* __restrict__ C,
    int block_m, int block_n)
{
    const int warp = threadIdx.x >> 5;
    const int wm   = warp & 1;
    const int wn   = warp >> 1;
#pragma unroll
    for (int j = 0; j < 4; j++) {
        wmma::fragment<wmma::accumulator, 16, 16, 16, float> bf;
        wmma::load_matrix_sync(bf, brep + block_n + wn * 64 + j * 16, 256, wmma::mem_row_major);
#pragma unroll
        for (int i = 0; i < 2; i++) {
            wmma::fragment<wmma::accumulator, 16, 16, 16, float> t;
#pragma unroll
            for (int e = 0; e < t.num_elements; e++) t.x[e] = acc[i][j].x[e] + bf.x[e];
            wmma::store_matrix_sync(C + (size_t)(block_m + wm * 32 + i * 16) * 256
                                      + block_n + wn * 64 + j * 16,
                                    t, 256, wmma::mem_row_major);
        }
    }
}

// ---------------------------------------------------------------------------
// Fused projection kernel (persistent): 1560 tiles over grid 444.
// ---------------------------------------------------------------------------
__global__ __launch_bounds__(128, 3)
void proj_fused_kernel(const __half* __restrict__ Af,
                       const __half* __restrict__ Aq,
                       const __half* __restrict__ Bv,
                       const __half* __restrict__ Boa,
                       const float* __restrict__ b_val,
                       const float* __restrict__ b_attn,
                       const float* __restrict__ brep_off,
                       const unsigned char* __restrict__ mask,
                       __half* __restrict__ Cval,
                       float* __restrict__ Coff,
                       float* __restrict__ Cattn,
                       int Mrows, int ntiles)
{
    extern __shared__ char smem[];
    const int tid = threadIdx.x;

    for (int t = blockIdx.x; t < ntiles; t += PGRID) {
        const int bx = t % 5;
        const int mt = t / 5;
        const bool is_val = (bx < 2);
        const int block_m = mt * 64;
        const int block_n = (is_val ? bx : bx - 2) * 128;

        wmma::fragment<wmma::accumulator, 16, 16, 16, float> acc[2][4];
        gemm_mainloop(is_val ? Af : Aq, is_val ? Bv : Boa, smem, block_m, block_n, Mrows, acc);

        if (bx == 2 || bx == 3) {
            if (block_m + 64 <= Mrows) {
                direct_epilogue(acc, brep_off, Coff, block_m, block_n);
                __syncthreads();
                continue;
            }
        }

        stage_acc(acc, smem);
        const float* stage = reinterpret_cast<const float*>(smem);
        const int r    = tid >> 1;
        const int colb = (tid & 1) * 64;
        const int gr   = block_m + r;
        if (gr < Mrows) {
            if (is_val) {
                const int prow = pad_row(gr);
                const float scale = (mask != nullptr && mask[gr]) ? 0.f : 1.f;
#pragma unroll
                for (int g = 0; g < 64; g += 16) {
                    const int gcol = block_n + colb + g;
                    __half hbuf[16];
#pragma unroll
                    for (int c = 0; c < 16; c++)
                        hbuf[c] = __float2half_rn((stage[r * CSTRIDE + colb + g + c] + __ldg(b_val + gcol + c)) * scale);
#pragma unroll
                    for (int c = 0; c < 16; c += 8)
                        *reinterpret_cast<uint4*>(Cval + (size_t)prow * 256 + gcol + c) =
                            *reinterpret_cast<uint4*>(hbuf + c);
                }
            } else if (bx == 4) {
#pragma unroll
                for (int g = 0; g < 64; g += 16) {
                    const int gc = colb + g;
                    float v[16];
#pragma unroll
                    for (int c = 0; c < 16; c++)
                        v[c] = stage[r * CSTRIDE + colb + g + c] + __ldg(b_attn + gc + c);
                    float mx = -1e30f;
#pragma unroll
                    for (int c = 0; c < 16; c++) mx = fmaxf(mx, v[c]);
                    float sum = 0.f;
#pragma unroll
                    for (int c = 0; c < 16; c++) { v[c] = __expf(v[c] - mx); sum += v[c]; }
                    float inv = 1.f / sum;
#pragma unroll
                    for (int c = 0; c < 16; c += 4) {
                        float4 o = make_float4(v[c]*inv, v[c+1]*inv, v[c+2]*inv, v[c+3]*inv);
                        *reinterpret_cast<float4*>(Cattn + (size_t)gr * 128 + gc + c) = o;
                    }
                }
            } else {
#pragma unroll
                for (int g = 0; g < 64; g += 16) {
                    const int gcol = block_n + colb + g;
                    float v[16];
#pragma unroll
                    for (int c = 0; c < 16; c++)
                        v[c] = stage[r * CSTRIDE + colb + g + c] + __ldg(brep_off + gcol + c);
#pragma unroll
                    for (int c = 0; c < 16; c += 4) {
                        float4 o = make_float4(v[c], v[c+1], v[c+2], v[c+3]);
                        *reinterpret_cast<float4*>(Coff + (size_t)gr * 256 + gcol + c) = o;
                    }
                }
            }
        }
        __syncthreads();
    }
}

// ---------------------------------------------------------------------------
// Output projection kernel (persistent): 624 tiles over grid 444.
// ---------------------------------------------------------------------------
__global__ __launch_bounds__(128, 3)
void proj_out_kernel(const __half* __restrict__ A,
                     const __half* __restrict__ B,
                     const float* __restrict__ brep_out,
                     float* __restrict__ C,
                     int Mrows, int ntiles)
{
    extern __shared__ char smem[];
    const int tid = threadIdx.x;

    for (int t = blockIdx.x; t < ntiles; t += PGRID) {
        const int block_n = (t & 1) * 128;
        const int block_m = (t >> 1) * 64;

        wmma::fragment<wmma::accumulator, 16, 16, 16, float> acc[2][4];
        gemm_mainloop(A, B, smem, block_m, block_n, Mrows, acc);

        if (block_m + 64 <= Mrows) {
            direct_epilogue(acc, brep_out, C, block_m, block_n);
        } else {
            stage_acc(acc, smem);
            const float* stage = reinterpret_cast<const float*>(smem);
            const int r    = tid >> 1;
            const int colb = (tid & 1) * 64;
            const int gr   = block_m + r;
            if (gr < Mrows) {
#pragma unroll
                for (int g = 0; g < 64; g += 16) {
                    const int gcol = block_n + colb + g;
                    float v[16];
#pragma unroll
                    for (int c = 0; c < 16; c++)
                        v[c] = stage[r * CSTRIDE + colb + g + c] + __ldg(brep_out + gcol + c);
#pragma unroll
                    for (int c = 0; c < 16; c += 4) {
                        float4 o = make_float4(v[c], v[c+1], v[c+2], v[c+3]);
                        *reinterpret_cast<float4*>(C + (size_t)gr * 256 + gcol + c) = o;
                    }
                }
            }
        }
        __syncthreads();
    }
}

// ---------------------------------------------------------------------------
// Sampler v7 (proven best)
// ---------------------------------------------------------------------------
__global__ __launch_bounds__(256)
void sample_kernel(const __half* __restrict__ value,
                   const float* __restrict__ off,
                   const float* __restrict__ aw,
                   const float* __restrict__ refp,
                   __half* __restrict__ mid)
{
    const int q    = blockIdx.x;
    const int m    = threadIdx.x >> 5;
    const int lane = threadIdx.x & 31;
    const int p2   = lane >> 3;
    const int c4   = lane & 7;

    const float offv = __ldg(off  + (size_t)q * 256 + m * 32 + lane);
    const float awv  = __ldg(aw   + (size_t)q * 128 + m * 16 + (lane & 15));
    const float rfv  = __ldg(refp + (size_t)q * 8 + (lane & 7));

    const int pt0 = lane & 15;
    const int l0  = pt0 >> 2;
    const float rx = __shfl_sync(0xffffffffu, rfv, l0 * 2 + 0);
    const float ry = __shfl_sync(0xffffffffu, rfv, l0 * 2 + 1);
    const float ox = __shfl_sync(0xffffffffu, offv, pt0 * 2 + 0);
    const float oy = __shfl_sync(0xffffffffu, offv, pt0 * 2 + 1);

    const float Wf = (l0 == 0) ? 150.f : (l0 == 1) ? 75.f : (l0 == 2) ? 38.f : 19.f;
    const float Hf = (l0 == 0) ? 100.f : (l0 == 1) ? 50.f : (l0 == 2) ? 25.f : 13.f;
    const int   Wp0 = (l0 == 0) ? 153 : (l0 == 1) ? 78 : (l0 == 2) ? 41 : 22;
    const int   SB0 = (l0 == 0) ? 154 : (l0 == 1) ? 15838 : (l0 == 2) ? 19935 : 21064;

    float x = fmaf(rx, Wf, ox) - 0.5f;
    float y = fmaf(ry, Hf, oy) - 0.5f;
    x = fminf(fmaxf(x, -1.f), Wf);
    y = fminf(fmaxf(y, -1.f), Hf);

    const float x0f = floorf(x), y0f = floorf(y);
    const float wx1 = x - x0f, wx0 = 1.f - wx1;
    const float wy1 = y - y0f, wy0 = 1.f - wy1;
    const int i00r = SB0 + (int)y0f * Wp0 + (int)x0f;

    __half2 pk01h = __floats2half2_rn(wx0 * wy0 * awv, wx1 * wy0 * awv);
    __half2 pk23h = __floats2half2_rn(wx0 * wy1 * awv, wx1 * wy1 * awv);
    const uint32_t pk01 = *reinterpret_cast<uint32_t*>(&pk01h);
    const uint32_t pk23 = *reinterpret_cast<uint32_t*>(&pk23h);

    const __half* vbase = value + m * DH + c4 * 4;
    float acc0 = 0.f, acc1 = 0.f, acc2 = 0.f, acc3 = 0.f;

    const int WPT[NLVL] = {153, 78, 41, 22};

#pragma unroll
    for (int l = 0; l < NLVL; l++) {
        const int src = l * 4 + p2;
        const int i00 = __shfl_sync(0xffffffffu, i00r, src);
        const uint32_t a01 = __shfl_sync(0xffffffffu, pk01, src);
        const uint32_t a23 = __shfl_sync(0xffffffffu, pk23, src);

        const __half2 h01 = *reinterpret_cast<const __half2*>(&a01);
        const __half2 h23 = *reinterpret_cast<const __half2*>(&a23);
        const __half2 W00 = __low2half2(h01),  W01 = __high2half2(h01);
        const __half2 W10 = __low2half2(h23),  W11 = __high2half2(h23);

        const int Wp = WPT[l];
        const __half* p00 = vbase + (size_t)i00 * 256;

        const uint2 u00 = __ldg(reinterpret_cast<const uint2*>(p00));
        const uint2 u01 = __ldg(reinterpret_cast<const uint2*>(p00 + 256));
        const uint2 u10 = __ldg(reinterpret_cast<const uint2*>(p00 + Wp * 256));
        const uint2 u11 = __ldg(reinterpret_cast<const uint2*>(p00 + (Wp + 1) * 256));

        __half2 sa = __hmul2(W00, *reinterpret_cast<const __half2*>(&u00.x));
        sa = __hfma2(W01, *reinterpret_cast<const __half2*>(&u01.x), sa);
        sa = __hfma2(W10, *reinterpret_cast<const __half2*>(&u10.x), sa);
        sa = __hfma2(W11, *reinterpret_cast<const __half2*>(&u11.x), sa);

        __half2 sb = __hmul2(W00, *reinterpret_cast<const __half2*>(&u00.y));
        sb = __hfma2(W01, *reinterpret_cast<const __half2*>(&u01.y), sb);
        sb = __hfma2(W10, *reinterpret_cast<const __half2*>(&u10.y), sb);
        sb = __hfma2(W11, *reinterpret_cast<const __half2*>(&u11.y), sb);

        const float2 fa = __half22float2(sa);
        const float2 fb = __half22float2(sb);
        acc0 += fa.x;
        acc1 += fa.y;
        acc2 += fb.x;
        acc3 += fb.y;
    }

    acc0 += __shfl_xor_sync(0xffffffffu, acc0, 8);
    acc1 += __shfl_xor_sync(0xffffffffu, acc1, 8);
    acc2 += __shfl_xor_sync(0xffffffffu, acc2, 8);
    acc3 += __shfl_xor_sync(0xffffffffu, acc3, 8);
    acc0 += __shfl_xor_sync(0xffffffffu, acc0, 16);
    acc1 += __shfl_xor_sync(0xffffffffu, acc1, 16);
    acc2 += __shfl_xor_sync(0xffffffffu, acc2, 16);
    acc3 += __shfl_xor_sync(0xffffffffu, acc3, 16);

    if (lane < 8) {
        __half2 h0 = __floats2half2_rn(acc0, acc1);
        __half2 h1 = __floats2half2_rn(acc2, acc3);
        uint2 u;
        u.x = *reinterpret_cast<uint32_t*>(&h0);
        u.y = *reinterpret_cast<uint32_t*>(&h1);
        *reinterpret_cast<uint2*>(mid + (size_t)q * 256 + m * DH + c4 * 4) = u;
    }
}

// ---------------------------------------------------------------------------
// Launch
// ---------------------------------------------------------------------------
extern "C" void kernel_launch(void* const* d_in, const int* in_sizes, int n_in,
                              void* d_out, int out_size)
{
    const float* query  = (const float*)d_in[0];
    const float* refp   = (const float*)d_in[1];
    const float* inflat = (const float*)d_in[2];
    const unsigned char* pmask = (const unsigned char*)d_in[3];
    const float* W_off  = (const float*)d_in[4];
    const float* b_off  = (const float*)d_in[5];
    const float* W_attn = (const float*)d_in[6];
    const float* b_attn = (const float*)d_in[7];
    const float* W_val  = (const float*)d_in[8];
    const float* b_val  = (const float*)d_in[9];
    const float* W_out  = (const float*)d_in[10];
    const float* b_out  = (const float*)d_in[11];
    float* out = (float*)d_out;

    __half* pvalp; cudaGetSymbolAddress((void**)&pvalp, g_value_pad);
    float*  poff;  cudaGetSymbolAddress((void**)&poff,  g_off);
    float*  pattn; cudaGetSymbolAddress((void**)&pattn, g_attn);
    float*  brep;  cudaGetSymbolAddress((void**)&brep,  g_brep);
    __half *q_h, *f_h, *w_h, *mid_h;
    cudaGetSymbolAddress((void**)&q_h,   g_q_h);
    cudaGetSymbolAddress((void**)&f_h,   g_f_h);
    cudaGetSymbolAddress((void**)&w_h,   g_w_h);
    cudaGetSymbolAddress((void**)&mid_h, g_mid_h);

    cudaFuncSetAttribute(proj_fused_kernel,
                         cudaFuncAttributeMaxDynamicSharedMemorySize, H_SMEM);
    cudaFuncSetAttribute(proj_out_kernel,
                         cudaFuncAttributeMaxDynamicSharedMemorySize, H_SMEM);

    const int Mr = LEN;
    const int mtiles = (Mr + 63) / 64;            // 312

    prep_all_kernel<<<(PREP_TOTAL + 255) / 256, 256>>>(
        W_val, W_off, W_attn, W_out, query, inflat, b_out, b_off,
        pvalp, w_h, q_h, f_h, brep);

    const __half* wv  = w_h;
    const __half* woa = w_h + 256 * 256;
    const __half* wu  = w_h + 640 * 256;
    const float* brep_out = brep;
    const float* brep_off = brep + 16 * 256;

    // 1. fused projections (persistent, grid 444)
    proj_fused_kernel<<<PGRID, 128, H_SMEM>>>(
        f_h, q_h, wv, woa, b_val, b_attn, brep_off, pmask, pvalp, poff, pattn,
        Mr, 5 * mtiles);
    // 2. sampler (v7)
    sample_kernel<<<Mr, 256>>>(pvalp, poff, pattn, refp, mid_h);
    // 3. output projection (persistent, grid 444)
    proj_out_kernel<<<PGRID, 128, H_SMEM>>>(mid_h, wu, brep_out, out, Mr, 2 * mtiles);
}